// round 14
// baseline (speedup 1.0000x reference)
#include <cuda_runtime.h>
#include <cuda_fp16.h>
#include <cstdint>

// ---------------- problem constants ----------------
#define BSZ   4096
#define MAXN  10
#define NVT   26
#define MAXPOS 9
#define HS    301
#define NZ    56
#define EMB   16
#define FEAT  8
#define VS    310
#define XDIM  35
#define DFD   27
#define GS    309
#define KP    304        // K padded (19*16)
#define NPG   320        // per-gang N padded
#define NG_GRU  (3*NPG)
#define NG_GATE (2*NPG)
#define NT    19         // K tiles of 16
#define NCID  (NVT*MAXPOS)   // 234

// ---------------- device scratch ----------------
__device__ float g_gated[(size_t)8 * BSZ * KP];
__device__ float g_Hin[(size_t)BSZ * KP];          // exact fp32 Hin (epilogue term)
__device__ __half g_Hinh[(size_t)BSZ * KP];        // fp16 GEMM image of Hin
__device__ __half g_Hvh [(size_t)BSZ * KP];        // fp16 GEMM image of Hv
__device__ float g_Hg [(size_t)BSZ * HS];
__device__ float g_Hd [(size_t)BSZ * FEAT];
__device__ int   g_n   [BSZ];
__device__ int   g_perm[BSZ];
__device__ int   g_nbs [BSZ];
__device__ int   g_cnt [MAXN + 1];
__device__ int   g_cid [BSZ * MAXN];
__device__ unsigned g_pmask[BSZ * MAXN];
__device__ __half g_Whh_h[(size_t)NG_GRU  * KP];
__device__ __half g_Wgm_h[(size_t)NG_GATE * KP];
__device__ float g_GI   [(size_t)NCID * 3 * KP];
__device__ float g_gateb[9 * KP];
__device__ float g_mapb [9 * KP];

__device__ __forceinline__ float sigm(float x) { return 1.f / (1.f + __expf(-x)); }
__device__ __forceinline__ void cp16(uint32_t dst, const void* src) {
    asm volatile("cp.async.cg.shared.global [%0], [%1], 16;" :: "r"(dst), "l"(src));
}
#define CP_COMMIT asm volatile("cp.async.commit_group;")
#define CP_WAIT1  asm volatile("cp.async.wait_group 1;")
#define CP_WAIT0  asm volatile("cp.async.wait_group 0;")

#define MMA_F16(C, A, b0, b1)                                                 \
    asm volatile(                                                             \
        "mma.sync.aligned.m16n8k16.row.col.f32.f16.f16.f32 "                  \
        "{%0,%1,%2,%3}, {%4,%5,%6,%7}, {%8,%9}, {%0,%1,%2,%3};"               \
        : "+f"((C)[0]), "+f"((C)[1]), "+f"((C)[2]), "+f"((C)[3])              \
        : "r"((A)[0]), "r"((A)[1]), "r"((A)[2]), "r"((A)[3]),                 \
          "r"(b0), "r"(b1))

// ================= merged prep: setup | gi | fp16 pack =================
__global__ void prep_kernel(const int* __restrict__ vc, const int* __restrict__ node_type,
                            const int* __restrict__ pos, const int* __restrict__ adj,
                            const float* __restrict__ r, const float* __restrict__ c_,
                            const float* __restrict__ gm,
                            const float* __restrict__ W1, const float* __restrict__ b1,
                            const float* __restrict__ W2, const float* __restrict__ b2,
                            const float* __restrict__ Wih, const float* __restrict__ bih,
                            const float* __restrict__ bhh,
                            const float* __restrict__ Whh,
                            const float* __restrict__ Wg, const float* __restrict__ bg,
                            const float* __restrict__ Wm)
{
    int bid = blockIdx.x;
    if (bid < 16) {
        int b = bid * 256 + threadIdx.x;
        if (b >= BSZ) return;
        int nb = vc[b]; nb = nb < 1 ? 1 : (nb > MAXN ? MAXN : nb);
        g_n[b] = nb;
        for (int v = 0; v < MAXN; ++v) {
            unsigned m = 0;
            if (v < nb)
                for (int u = 0; u < v; ++u)
                    if (adj[(size_t)b * 100 + u * 10 + v]) m |= 1u << u;
            g_pmask[b * MAXN + v] = m;
            g_cid[b * MAXN + v] = node_type[b * MAXN + v] * MAXPOS + pos[b * MAXN + v];
        }
        float df[DFD];
#pragma unroll
        for (int d = 0; d < DFD; ++d) df[d] = 0.f;
        for (int v = 0; v < MAXN; ++v) {
            if (v < nb) {
                int p = pos[b * MAXN + v] * 3;
                df[p]     = r [b * MAXN + v];
                df[p + 1] = c_[b * MAXN + v];
                df[p + 2] = gm[b * MAXN + v];
            }
        }
        float t16[EMB];
#pragma unroll
        for (int e = 0; e < EMB; ++e) {
            float s = b1[e];
#pragma unroll
            for (int d = 0; d < DFD; ++d) s += df[d] * W1[e * DFD + d];
            t16[e] = fmaxf(s, 0.f);
        }
#pragma unroll
        for (int f = 0; f < FEAT; ++f) {
            float s = b2[f];
#pragma unroll
            for (int e = 0; e < EMB; ++e) s += t16[e] * W2[f * EMB + e];
            g_Hd[b * FEAT + f] = s;
        }
    } else if (bid < 16 + NCID) {
        int cid = bid - 16;
        int t = cid / MAXPOS, p = cid % MAXPOS;
        for (int idx = threadIdx.x; idx < 3 * KP; idx += blockDim.x) {
            int gg = idx / KP, h = idx % KP;
            float v = 0.f;
            if (h < HS) {
                int row = gg * HS + h;
                v = Wih[row * XDIM + t] + Wih[row * XDIM + NVT + p] + bih[row];
                if (gg < 2) v += bhh[row];
            }
            g_GI[(size_t)cid * 3 * KP + idx] = v;
        }
    } else {
        int idx = (bid - 16 - NCID) * 256 + threadIdx.x;
        const int tot1 = NG_GRU * KP, tot2 = NG_GATE * KP, tot3 = 9 * KP;
        if (idx < tot1) {
            int row = idx / KP, k = idx % KP;
            int gg = row / NPG, n = row % NPG;
            float v = (n < HS && k < HS) ? Whh[(size_t)(gg * HS + n) * HS + k] : 0.f;
            g_Whh_h[idx] = __float2half_rn(v);
        } else if (idx < tot1 + tot2) {
            int j = idx - tot1;
            int row = j / KP, k = j % KP;
            int gg = row / NPG, n = row % NPG;
            const float* src = gg ? Wm : Wg;
            float v = (n < HS && k < HS) ? src[(size_t)n * VS + k] : 0.f;
            g_Wgm_h[j] = __float2half_rn(v);
        } else if (idx < tot1 + tot2 + tot3) {
            int j = idx - tot1 - tot2;
            int p = j / KP, h = j % KP;
            g_gateb[j] = (h < HS) ? bg[h] + Wg[(size_t)h * VS + HS + p] : 0.f;
        } else if (idx < tot1 + tot2 + 2 * tot3) {
            int j = idx - tot1 - tot2 - tot3;
            int p = j / KP, h = j % KP;
            g_mapb[j] = (h < HS) ? Wm[(size_t)h * VS + HS + p] : 0.f;
        }
    }
}

// ---------------- counting sort by nb (descending) ----------------
__global__ void sort_kernel()
{
    __shared__ int cnt_s[16], start_s[16], cur_s[16];
    int tid = threadIdx.x;
    if (tid < 16) cnt_s[tid] = 0;
    __syncthreads();
    for (int b = tid; b < BSZ; b += blockDim.x) atomicAdd(&cnt_s[g_n[b]], 1);
    __syncthreads();
    if (tid == 0) {
        int run = 0;
        for (int k = MAXN; k >= 1; --k) { start_s[k] = run; run += cnt_s[k]; }
        for (int v = 0; v <= MAXN; ++v) {
            int s = 0;
            for (int k = v + 1; k <= MAXN; ++k) s += cnt_s[k];
            g_cnt[v] = s;
        }
        for (int k = 1; k <= MAXN; ++k) cur_s[k] = start_s[k];
    }
    __syncthreads();
    for (int b = tid; b < BSZ; b += blockDim.x) {
        int k = g_n[b];
        int idx = atomicAdd(&cur_s[k], 1);
        g_perm[idx] = b;
        g_nbs[idx] = k;
    }
}

// ================= GRU step: BM=32, 3-stage pipeline, 3-gang fp16 GEMM + epilogue ========
// 8 warps: each warp = full 32 rows x one 8-col slice per gang (wn = warp)
__global__ void __launch_bounds__(256) gru_step(int v, int has_agg,
                                                const float* __restrict__ bhh)
{
    const int tid = threadIdx.x, warp = tid >> 5, lane = tid & 31;
    const int wn = warp, g = lane >> 2, tg = lane & 3;
    const int bm = blockIdx.x * 32, bn = blockIdx.y * 64;
    const int cntv = g_cnt[v];
    if (bm >= cntv) return;

    __shared__ __align__(16) __half As[3][32][24];
    __shared__ __align__(16) __half Bs[3][192][24];

    float acc[3][2][4];
#pragma unroll
    for (int gg = 0; gg < 3; ++gg)
#pragma unroll
        for (int mi = 0; mi < 2; ++mi)
#pragma unroll
            for (int q = 0; q < 4; ++q) acc[gg][mi][q] = 0.f;

    if (has_agg) {
        const uint32_t sA = (uint32_t)__cvta_generic_to_shared(&As[0][0][0]);
        const uint32_t sB = (uint32_t)__cvta_generic_to_shared(&Bs[0][0][0]);
        const int rowh = tid >> 1, half = tid & 1;
#pragma unroll
        for (int pre = 0; pre < 2; ++pre) {
            int k0 = pre * 16;
            if (tid < 64)
                cp16(sA + (pre * 768 + rowh * 24 + half * 8) * 2,
                     g_Hinh + (size_t)(bm + rowh) * KP + k0 + half * 8);
            for (int i = tid; i < 384; i += 256) {
                int rh = i >> 1, hf = i & 1;
                int gg = rh >> 6, n = rh & 63;
                cp16(sB + (pre * 4608 + rh * 24 + hf * 8) * 2,
                     g_Whh_h + (size_t)(gg * NPG + bn + n) * KP + k0 + hf * 8);
            }
            CP_COMMIT;
        }
        for (int kt = 0; kt < NT; ++kt) {
            int cur = kt % 3;
            if (kt == NT - 1) { CP_WAIT0; } else { CP_WAIT1; }
            __syncthreads();
            if (kt + 2 < NT) {
                int nxt = (kt + 2) % 3;
                int k0 = (kt + 2) * 16;
                if (tid < 64)
                    cp16(sA + (nxt * 768 + rowh * 24 + half * 8) * 2,
                         g_Hinh + (size_t)(bm + rowh) * KP + k0 + half * 8);
                for (int i = tid; i < 384; i += 256) {
                    int rh = i >> 1, hf = i & 1;
                    int gg = rh >> 6, n = rh & 63;
                    cp16(sB + (nxt * 4608 + rh * 24 + hf * 8) * 2,
                         g_Whh_h + (size_t)(gg * NPG + bn + n) * KP + k0 + hf * 8);
                }
                CP_COMMIT;
            }
            uint32_t af[2][4];
#pragma unroll
            for (int mi = 0; mi < 2; ++mi) {
                int rb = mi * 16;
                af[mi][0] = *(const uint32_t*)&As[cur][rb + g    ][2 * tg];
                af[mi][1] = *(const uint32_t*)&As[cur][rb + g + 8][2 * tg];
                af[mi][2] = *(const uint32_t*)&As[cur][rb + g    ][2 * tg + 8];
                af[mi][3] = *(const uint32_t*)&As[cur][rb + g + 8][2 * tg + 8];
            }
#pragma unroll
            for (int gg = 0; gg < 3; ++gg) {
                int row = gg * 64 + wn * 8 + g;
                uint32_t b0 = *(const uint32_t*)&Bs[cur][row][2 * tg];
                uint32_t b1 = *(const uint32_t*)&Bs[cur][row][2 * tg + 8];
#pragma unroll
                for (int mi = 0; mi < 2; ++mi)
                    MMA_F16(acc[gg][mi], af[mi], b0, b1);
            }
        }
    }

    // ---- fused GRU epilogue ----
#pragma unroll
    for (int mi = 0; mi < 2; ++mi) {
#pragma unroll
        for (int rr = 0; rr < 2; ++rr) {
            int i = bm + mi * 16 + g + rr * 8;
            int orig = g_perm[i];
            int cid  = g_cid[orig * MAXN + v];
            int nbi  = g_nbs[i];
            bool valid = (i < cntv);
            const float* GIrow = g_GI + (size_t)cid * 3 * KP;
            int q0 = 2 * rr, q1 = 2 * rr + 1;
            int j = bn + wn * 8 + 2 * tg;
            if (j >= HS) continue;
            float2 GIr = *(const float2*)(GIrow + j);
            float2 GIz = *(const float2*)(GIrow + KP + j);
            float2 GIn = *(const float2*)(GIrow + 2 * KP + j);
            float bn0 = bhh[2 * HS + j];
            float bn1 = (j + 1 < HS) ? bhh[2 * HS + j + 1] : 0.f;
            float hin0 = 0.f, hin1 = 0.f;
            if (has_agg) {
                float2 t = *(const float2*)(g_Hin + (size_t)i * KP + j);
                hin0 = t.x; hin1 = t.y;
            }
            float rg0 = sigm(GIr.x + acc[0][mi][q0]);
            float zg0 = sigm(GIz.x + acc[1][mi][q0]);
            float ng0 = tanhf(GIn.x + rg0 * (acc[2][mi][q0] + bn0));
            float hv0 = (1.f - zg0) * ng0 + zg0 * hin0;
            float rg1 = sigm(GIr.y + acc[0][mi][q1]);
            float zg1 = sigm(GIz.y + acc[1][mi][q1]);
            float ng1 = tanhf(GIn.y + rg1 * (acc[2][mi][q1] + bn1));
            float hv1 = (1.f - zg1) * ng1 + zg1 * hin1;
            if (!valid) { hv0 = 0.f; hv1 = 0.f; }
            if (j + 1 >= HS) hv1 = 0.f;
            *(__half2*)&g_Hvh[(size_t)i * KP + j] = __floats2half2_rn(hv0, hv1);
            if (valid && v == nbi - 1) {
                g_Hg[(size_t)orig * HS + j] = hv0;
                if (j + 1 < HS) g_Hg[(size_t)orig * HS + j + 1] = hv1;
            }
        }
    }
}

// ================= gate step: BM=32, 3-stage pipeline, 2-gang fp16 GEMM + epilogue =======
__global__ void __launch_bounds__(256) gate_step(int v)
{
    const int tid = threadIdx.x, warp = tid >> 5, lane = tid & 31;
    const int wn = warp, g = lane >> 2, tg = lane & 3;
    const int bm = blockIdx.x * 32, bn = blockIdx.y * 64;
    const int cntv = g_cnt[v + 1];
    if (bm >= cntv) return;

    __shared__ __align__(16) __half As[3][32][24];
    __shared__ __align__(16) __half Bs[3][128][24];

    float acc[2][2][4];
#pragma unroll
    for (int gg = 0; gg < 2; ++gg)
#pragma unroll
        for (int mi = 0; mi < 2; ++mi)
#pragma unroll
            for (int q = 0; q < 4; ++q) acc[gg][mi][q] = 0.f;

    {
        const uint32_t sA = (uint32_t)__cvta_generic_to_shared(&As[0][0][0]);
        const uint32_t sB = (uint32_t)__cvta_generic_to_shared(&Bs[0][0][0]);
        const int rowh = tid >> 1, half = tid & 1;
        const int gg0 = rowh >> 6, n0 = rowh & 63;
#pragma unroll
        for (int pre = 0; pre < 2; ++pre) {
            int k0 = pre * 16;
            if (tid < 64)
                cp16(sA + (pre * 768 + rowh * 24 + half * 8) * 2,
                     g_Hvh + (size_t)(bm + rowh) * KP + k0 + half * 8);
            cp16(sB + (pre * 3072 + rowh * 24 + half * 8) * 2,
                 g_Wgm_h + (size_t)(gg0 * NPG + bn + n0) * KP + k0 + half * 8);
            CP_COMMIT;
        }
        for (int kt = 0; kt < NT; ++kt) {
            int cur = kt % 3;
            if (kt == NT - 1) { CP_WAIT0; } else { CP_WAIT1; }
            __syncthreads();
            if (kt + 2 < NT) {
                int nxt = (kt + 2) % 3;
                int k0 = (kt + 2) * 16;
                if (tid < 64)
                    cp16(sA + (nxt * 768 + rowh * 24 + half * 8) * 2,
                         g_Hvh + (size_t)(bm + rowh) * KP + k0 + half * 8);
                cp16(sB + (nxt * 3072 + rowh * 24 + half * 8) * 2,
                     g_Wgm_h + (size_t)(gg0 * NPG + bn + n0) * KP + k0 + half * 8);
                CP_COMMIT;
            }
            uint32_t af[2][4];
#pragma unroll
            for (int mi = 0; mi < 2; ++mi) {
                int rb = mi * 16;
                af[mi][0] = *(const uint32_t*)&As[cur][rb + g    ][2 * tg];
                af[mi][1] = *(const uint32_t*)&As[cur][rb + g + 8][2 * tg];
                af[mi][2] = *(const uint32_t*)&As[cur][rb + g    ][2 * tg + 8];
                af[mi][3] = *(const uint32_t*)&As[cur][rb + g + 8][2 * tg + 8];
            }
#pragma unroll
            for (int gg = 0; gg < 2; ++gg) {
                int row = gg * 64 + wn * 8 + g;
                uint32_t b0 = *(const uint32_t*)&Bs[cur][row][2 * tg];
                uint32_t b1 = *(const uint32_t*)&Bs[cur][row][2 * tg + 8];
#pragma unroll
                for (int mi = 0; mi < 2; ++mi)
                    MMA_F16(acc[gg][mi], af[mi], b0, b1);
            }
        }
    }

    // ---- fused gate epilogue + Hin(v+1) ----
#pragma unroll
    for (int mi = 0; mi < 2; ++mi) {
#pragma unroll
        for (int rr = 0; rr < 2; ++rr) {
            int i = bm + mi * 16 + g + rr * 8;
            int orig = g_perm[i];
            int pv = g_cid[orig * MAXN + v] % MAXPOS;
            unsigned mask = g_pmask[orig * MAXN + v + 1];
            int q0 = 2 * rr, q1 = 2 * rr + 1;
            int j = bn + wn * 8 + 2 * tg;
            if (j >= HS) continue;
            float2 gb = *(const float2*)(g_gateb + pv * KP + j);
            float2 mb = *(const float2*)(g_mapb + pv * KP + j);
            float gv0 = sigm(acc[0][mi][q0] + gb.x) * (acc[1][mi][q0] + mb.x);
            float gv1 = sigm(acc[0][mi][q1] + gb.y) * (acc[1][mi][q1] + mb.y);
            if (j + 1 >= HS) gv1 = 0.f;
            *(float2*)(g_gated + ((size_t)v * BSZ + i) * KP + j) = make_float2(gv0, gv1);
            float s0 = 0.f, s1 = 0.f;
            for (int u = 0; u < v; ++u)
                if ((mask >> u) & 1u) {
                    float2 t = *(const float2*)(g_gated + ((size_t)u * BSZ + i) * KP + j);
                    s0 += t.x; s1 += t.y;
                }
            if ((mask >> v) & 1u) { s0 += gv0; s1 += gv1; }
            *(float2*)(g_Hin + (size_t)i * KP + j) = make_float2(s0, s1);
            *(__half2*)&g_Hinh[(size_t)i * KP + j] = __floats2half2_rn(s0, s1);
        }
    }
}

// ---------------- heads ----------------
__global__ void final_kernel(const float* __restrict__ Wmu, const float* __restrict__ bmu,
                             const float* __restrict__ Wlv, const float* __restrict__ blv,
                             float* __restrict__ out)
{
    __shared__ float sh[8][GS + 3];
    int b0 = blockIdx.x * 8;
    for (int idx = threadIdx.x; idx < 8 * HS; idx += blockDim.x) {
        int i = idx / HS, k = idx % HS;
        sh[i][k] = g_Hg[(size_t)(b0 + i) * HS + k];
    }
    for (int idx = threadIdx.x; idx < 8 * FEAT; idx += blockDim.x) {
        int i = idx / FEAT, f = idx % FEAT;
        sh[i][HS + f] = g_Hd[(b0 + i) * FEAT + f];
    }
    __syncthreads();
    int t = threadIdx.x;
    if (t < 2 * NZ) {
        int head = t / NZ;
        int o = t % NZ;
        const float* W = head ? Wlv : Wmu;
        float bias = head ? blv[o] : bmu[o];
        float acc[8];
#pragma unroll
        for (int i = 0; i < 8; ++i) acc[i] = 0.f;
        for (int k = 0; k < GS; ++k) {
            float wv = W[o * GS + k];
#pragma unroll
            for (int i = 0; i < 8; ++i) acc[i] += sh[i][k] * wv;
        }
#pragma unroll
        for (int i = 0; i < 8; ++i)
            out[(size_t)head * BSZ * NZ + (size_t)(b0 + i) * NZ + o] = acc[i] + bias;
    }
}

// ---------------- launch ----------------
extern "C" void kernel_launch(void* const* d_in, const int* in_sizes, int n_in,
                              void* d_out, int out_size)
{
    const int*   node_type = (const int*)  d_in[0];
    const int*   pos       = (const int*)  d_in[1];
    const int*   adj       = (const int*)  d_in[2];
    const int*   vcount    = (const int*)  d_in[3];
    const float* r         = (const float*)d_in[4];
    const float* c         = (const float*)d_in[5];
    const float* gm        = (const float*)d_in[6];
    const float* Wih       = (const float*)d_in[7];
    const float* Whh       = (const float*)d_in[8];
    const float* bih       = (const float*)d_in[9];
    const float* bhh       = (const float*)d_in[10];
    const float* Wg        = (const float*)d_in[11];
    const float* bg        = (const float*)d_in[12];
    const float* Wm        = (const float*)d_in[13];
    const float* W1        = (const float*)d_in[14];
    const float* b1        = (const float*)d_in[15];
    const float* W2        = (const float*)d_in[16];
    const float* b2        = (const float*)d_in[17];
    const float* Wmu       = (const float*)d_in[18];
    const float* bmu       = (const float*)d_in[19];
    const float* Wlv       = (const float*)d_in[20];
    const float* blv       = (const float*)d_in[21];
    float* out = (float*)d_out;

    const int tot_pack = (NG_GRU + NG_GATE) * KP + 2 * 9 * KP;
    const int pack_blocks = (tot_pack + 255) / 256;
    prep_kernel<<<16 + NCID + pack_blocks, 256>>>(
        vcount, node_type, pos, adj, r, c, gm, W1, b1, W2, b2,
        Wih, bih, bhh, Whh, Wg, bg, Wm);
    sort_kernel<<<1, 1024>>>();

    dim3 grid(128, 5);
    gru_step<<<grid, 256>>>(0, 0, bhh);
    for (int v = 0; v < 8; ++v) {
        gate_step<<<grid, 256>>>(v);
        gru_step<<<grid, 256>>>(v + 1, 1, bhh);
    }
    final_kernel<<<BSZ / 8, 128>>>(Wmu, bmu, Wlv, blv, out);
}

// round 15
// speedup vs baseline: 1.1060x; 1.1060x over previous
#include <cuda_runtime.h>
#include <cuda_fp16.h>
#include <cstdint>

// ---------------- problem constants ----------------
#define BSZ   4096
#define MAXN  10
#define NVT   26
#define MAXPOS 9
#define HS    301
#define NZ    56
#define EMB   16
#define FEAT  8
#define VS    310
#define XDIM  35
#define DFD   27
#define GS    309
#define KP    304        // K padded (19*16)
#define NPG   320        // per-gang N padded
#define NG_GRU  (3*NPG)
#define NG_GATE (2*NPG)
#define NT    19         // K tiles of 16
#define NCID  (NVT*MAXPOS)   // 234

// ---------------- device scratch ----------------
__device__ float g_gated[(size_t)8 * BSZ * KP];
__device__ float g_Hin[(size_t)BSZ * KP];          // exact fp32 Hin (epilogue term)
__device__ __half g_Hinh[(size_t)BSZ * KP];        // fp16 GEMM image of Hin
__device__ __half g_Hvh [(size_t)BSZ * KP];        // fp16 GEMM image of Hv
__device__ float g_Hg [(size_t)BSZ * HS];
__device__ float g_Hd [(size_t)BSZ * FEAT];
__device__ int   g_n   [BSZ];
__device__ int   g_perm[BSZ];
__device__ int   g_nbs [BSZ];
__device__ int   g_cnt [MAXN + 1];
__device__ int   g_cid [BSZ * MAXN];
__device__ unsigned g_pmask[BSZ * MAXN];
__device__ __half g_Whh_h[(size_t)NG_GRU  * KP];
__device__ __half g_Wgm_h[(size_t)NG_GATE * KP];
__device__ float g_GI   [(size_t)NCID * 3 * KP];
__device__ float g_gateb[9 * KP];
__device__ float g_mapb [9 * KP];

__device__ __forceinline__ float sigm(float x) { return 1.f / (1.f + __expf(-x)); }
__device__ __forceinline__ void cp16(uint32_t dst, const void* src) {
    asm volatile("cp.async.cg.shared.global [%0], [%1], 16;" :: "r"(dst), "l"(src));
}
#define CP_COMMIT asm volatile("cp.async.commit_group;")
#define CP_WAIT1  asm volatile("cp.async.wait_group 1;")
#define CP_WAIT0  asm volatile("cp.async.wait_group 0;")

#define MMA_F16(C, A, b0, b1)                                                 \
    asm volatile(                                                             \
        "mma.sync.aligned.m16n8k16.row.col.f32.f16.f16.f32 "                  \
        "{%0,%1,%2,%3}, {%4,%5,%6,%7}, {%8,%9}, {%0,%1,%2,%3};"               \
        : "+f"((C)[0]), "+f"((C)[1]), "+f"((C)[2]), "+f"((C)[3])              \
        : "r"((A)[0]), "r"((A)[1]), "r"((A)[2]), "r"((A)[3]),                 \
          "r"(b0), "r"(b1))

__device__ __forceinline__ void ldsm4(uint32_t* r, uint32_t addr) {
    asm volatile("ldmatrix.sync.aligned.m8n8.x4.shared.b16 {%0,%1,%2,%3}, [%4];"
                 : "=r"(r[0]), "=r"(r[1]), "=r"(r[2]), "=r"(r[3]) : "r"(addr));
}

// ================= merged prep: setup | gi | fp16 pack =================
__global__ void prep_kernel(const int* __restrict__ vc, const int* __restrict__ node_type,
                            const int* __restrict__ pos, const int* __restrict__ adj,
                            const float* __restrict__ r, const float* __restrict__ c_,
                            const float* __restrict__ gm,
                            const float* __restrict__ W1, const float* __restrict__ b1,
                            const float* __restrict__ W2, const float* __restrict__ b2,
                            const float* __restrict__ Wih, const float* __restrict__ bih,
                            const float* __restrict__ bhh,
                            const float* __restrict__ Whh,
                            const float* __restrict__ Wg, const float* __restrict__ bg,
                            const float* __restrict__ Wm)
{
    int bid = blockIdx.x;
    if (bid < 16) {
        int b = bid * 256 + threadIdx.x;
        if (b >= BSZ) return;
        int nb = vc[b]; nb = nb < 1 ? 1 : (nb > MAXN ? MAXN : nb);
        g_n[b] = nb;
        for (int v = 0; v < MAXN; ++v) {
            unsigned m = 0;
            if (v < nb)
                for (int u = 0; u < v; ++u)
                    if (adj[(size_t)b * 100 + u * 10 + v]) m |= 1u << u;
            g_pmask[b * MAXN + v] = m;
            g_cid[b * MAXN + v] = node_type[b * MAXN + v] * MAXPOS + pos[b * MAXN + v];
        }
        float df[DFD];
#pragma unroll
        for (int d = 0; d < DFD; ++d) df[d] = 0.f;
        for (int v = 0; v < MAXN; ++v) {
            if (v < nb) {
                int p = pos[b * MAXN + v] * 3;
                df[p]     = r [b * MAXN + v];
                df[p + 1] = c_[b * MAXN + v];
                df[p + 2] = gm[b * MAXN + v];
            }
        }
        float t16[EMB];
#pragma unroll
        for (int e = 0; e < EMB; ++e) {
            float s = b1[e];
#pragma unroll
            for (int d = 0; d < DFD; ++d) s += df[d] * W1[e * DFD + d];
            t16[e] = fmaxf(s, 0.f);
        }
#pragma unroll
        for (int f = 0; f < FEAT; ++f) {
            float s = b2[f];
#pragma unroll
            for (int e = 0; e < EMB; ++e) s += t16[e] * W2[f * EMB + e];
            g_Hd[b * FEAT + f] = s;
        }
    } else if (bid < 16 + NCID) {
        int cid = bid - 16;
        int t = cid / MAXPOS, p = cid % MAXPOS;
        for (int idx = threadIdx.x; idx < 3 * KP; idx += blockDim.x) {
            int gg = idx / KP, h = idx % KP;
            float v = 0.f;
            if (h < HS) {
                int row = gg * HS + h;
                v = Wih[row * XDIM + t] + Wih[row * XDIM + NVT + p] + bih[row];
                if (gg < 2) v += bhh[row];
            }
            g_GI[(size_t)cid * 3 * KP + idx] = v;
        }
    } else {
        int idx = (bid - 16 - NCID) * 256 + threadIdx.x;
        const int tot1 = NG_GRU * KP, tot2 = NG_GATE * KP, tot3 = 9 * KP;
        if (idx < tot1) {
            int row = idx / KP, k = idx % KP;
            int gg = row / NPG, n = row % NPG;
            float v = (n < HS && k < HS) ? Whh[(size_t)(gg * HS + n) * HS + k] : 0.f;
            g_Whh_h[idx] = __float2half_rn(v);
        } else if (idx < tot1 + tot2) {
            int j = idx - tot1;
            int row = j / KP, k = j % KP;
            int gg = row / NPG, n = row % NPG;
            const float* src = gg ? Wm : Wg;
            float v = (n < HS && k < HS) ? src[(size_t)n * VS + k] : 0.f;
            g_Wgm_h[j] = __float2half_rn(v);
        } else if (idx < tot1 + tot2 + tot3) {
            int j = idx - tot1 - tot2;
            int p = j / KP, h = j % KP;
            g_gateb[j] = (h < HS) ? bg[h] + Wg[(size_t)h * VS + HS + p] : 0.f;
        } else if (idx < tot1 + tot2 + 2 * tot3) {
            int j = idx - tot1 - tot2 - tot3;
            int p = j / KP, h = j % KP;
            g_mapb[j] = (h < HS) ? Wm[(size_t)h * VS + HS + p] : 0.f;
        }
    }
}

// ---------------- counting sort by nb (descending) ----------------
__global__ void sort_kernel()
{
    __shared__ int cnt_s[16], start_s[16], cur_s[16];
    int tid = threadIdx.x;
    if (tid < 16) cnt_s[tid] = 0;
    __syncthreads();
    for (int b = tid; b < BSZ; b += blockDim.x) atomicAdd(&cnt_s[g_n[b]], 1);
    __syncthreads();
    if (tid == 0) {
        int run = 0;
        for (int k = MAXN; k >= 1; --k) { start_s[k] = run; run += cnt_s[k]; }
        for (int v = 0; v <= MAXN; ++v) {
            int s = 0;
            for (int k = v + 1; k <= MAXN; ++k) s += cnt_s[k];
            g_cnt[v] = s;
        }
        for (int k = 1; k <= MAXN; ++k) cur_s[k] = start_s[k];
    }
    __syncthreads();
    for (int b = tid; b < BSZ; b += blockDim.x) {
        int k = g_n[b];
        int idx = atomicAdd(&cur_s[k], 1);
        g_perm[idx] = b;
        g_nbs[idx] = k;
    }
}

// ================= GRU step: BM=64, unrolled 3-stage pipeline, ldmatrix fragments ========
__global__ void __launch_bounds__(256) gru_step(int v, int has_agg,
                                                const float* __restrict__ bhh)
{
    const int tid = threadIdx.x, warp = tid >> 5, lane = tid & 31;
    const int wm = warp & 1, wn = warp >> 1, g = lane >> 2, tg = lane & 3;
    const int bm = blockIdx.x * 64, bn = blockIdx.y * 64;
    const int cntv = g_cnt[v];
    if (bm >= cntv) return;

    __shared__ __align__(16) __half As[3][64][24];
    __shared__ __align__(16) __half Bs[3][192][24];

    float acc[3][2][2][4];
#pragma unroll
    for (int gg = 0; gg < 3; ++gg)
#pragma unroll
        for (int mi = 0; mi < 2; ++mi)
#pragma unroll
            for (int ni = 0; ni < 2; ++ni)
#pragma unroll
                for (int q = 0; q < 4; ++q) acc[gg][mi][ni][q] = 0.f;

    if (has_agg) {
        const uint32_t sA = (uint32_t)__cvta_generic_to_shared(&As[0][0][0]);
        const uint32_t sB = (uint32_t)__cvta_generic_to_shared(&Bs[0][0][0]);
        const int rowh = tid >> 1, half = tid & 1;
        // per-lane ldmatrix base addresses (row stride 48B; k-half offset 16B)
        const uint32_t lmoff = (uint32_t)((((lane >> 3) & 1) * 8 + (lane & 7)) * 48
                                          + (lane >> 4) * 16);
        const uint32_t aF = sA + lmoff + (uint32_t)(wm * 32) * 48;
        const uint32_t bF = sB + lmoff + (uint32_t)(wn * 16) * 48;
        const __half* pA = g_Hinh + (size_t)(bm + rowh) * KP + half * 8;

#pragma unroll
        for (int pre = 0; pre < 2; ++pre) {
            int k0 = pre * 16;
            if (tid < 128)
                cp16(sA + pre * 3072 + (uint32_t)(rowh * 48 + half * 16), pA + k0);
            for (int i = tid; i < 384; i += 256) {
                int rh = i >> 1, hf = i & 1;
                int gg = rh >> 6, n = rh & 63;
                cp16(sB + pre * 9216 + (uint32_t)(rh * 48 + hf * 16),
                     g_Whh_h + (size_t)(gg * NPG + bn + n) * KP + k0 + hf * 8);
            }
            CP_COMMIT;
        }
#pragma unroll
        for (int kt = 0; kt < NT; ++kt) {
            const int cur = kt % 3;
            if (kt == NT - 1) { CP_WAIT0; } else { CP_WAIT1; }
            __syncthreads();
            if (kt + 2 < NT) {
                const int nxt = (kt + 2) % 3;
                const int k0 = (kt + 2) * 16;
                if (tid < 128)
                    cp16(sA + nxt * 3072 + (uint32_t)(rowh * 48 + half * 16), pA + k0);
                for (int i = tid; i < 384; i += 256) {
                    int rh = i >> 1, hf = i & 1;
                    int gg = rh >> 6, n = rh & 63;
                    cp16(sB + nxt * 9216 + (uint32_t)(rh * 48 + hf * 16),
                         g_Whh_h + (size_t)(gg * NPG + bn + n) * KP + k0 + hf * 8);
                }
                CP_COMMIT;
            }
            uint32_t a0[4], a1[4];
            ldsm4(a0, aF + cur * 3072);
            ldsm4(a1, aF + cur * 3072 + 768);
#pragma unroll
            for (int gg = 0; gg < 3; ++gg) {
                uint32_t b[4];
                ldsm4(b, bF + cur * 9216 + gg * 3072);
                MMA_F16(acc[gg][0][0], a0, b[0], b[2]);
                MMA_F16(acc[gg][0][1], a0, b[1], b[3]);
                MMA_F16(acc[gg][1][0], a1, b[0], b[2]);
                MMA_F16(acc[gg][1][1], a1, b[1], b[3]);
            }
        }
    }

    // ---- fused GRU epilogue ----
#pragma unroll
    for (int mi = 0; mi < 2; ++mi) {
#pragma unroll
        for (int rr = 0; rr < 2; ++rr) {
            int i = bm + wm * 32 + mi * 16 + g + rr * 8;
            int orig = g_perm[i];
            int cid  = g_cid[orig * MAXN + v];
            int nbi  = g_nbs[i];
            bool valid = (i < cntv);
            const float* GIrow = g_GI + (size_t)cid * 3 * KP;
            int q0 = 2 * rr, q1 = 2 * rr + 1;
#pragma unroll
            for (int ni = 0; ni < 2; ++ni) {
                int j = bn + wn * 16 + ni * 8 + 2 * tg;
                if (j >= HS) continue;
                float2 GIr = *(const float2*)(GIrow + j);
                float2 GIz = *(const float2*)(GIrow + KP + j);
                float2 GIn = *(const float2*)(GIrow + 2 * KP + j);
                float bn0 = bhh[2 * HS + j];
                float bn1 = (j + 1 < HS) ? bhh[2 * HS + j + 1] : 0.f;
                float hin0 = 0.f, hin1 = 0.f;
                if (has_agg) {
                    float2 t = *(const float2*)(g_Hin + (size_t)i * KP + j);
                    hin0 = t.x; hin1 = t.y;
                }
                float rg0 = sigm(GIr.x + acc[0][mi][ni][q0]);
                float zg0 = sigm(GIz.x + acc[1][mi][ni][q0]);
                float ng0 = tanhf(GIn.x + rg0 * (acc[2][mi][ni][q0] + bn0));
                float hv0 = (1.f - zg0) * ng0 + zg0 * hin0;
                float rg1 = sigm(GIr.y + acc[0][mi][ni][q1]);
                float zg1 = sigm(GIz.y + acc[1][mi][ni][q1]);
                float ng1 = tanhf(GIn.y + rg1 * (acc[2][mi][ni][q1] + bn1));
                float hv1 = (1.f - zg1) * ng1 + zg1 * hin1;
                if (!valid) { hv0 = 0.f; hv1 = 0.f; }
                if (j + 1 >= HS) hv1 = 0.f;
                *(__half2*)&g_Hvh[(size_t)i * KP + j] = __floats2half2_rn(hv0, hv1);
                if (valid && v == nbi - 1) {
                    g_Hg[(size_t)orig * HS + j] = hv0;
                    if (j + 1 < HS) g_Hg[(size_t)orig * HS + j + 1] = hv1;
                }
            }
        }
    }
}

// ================= gate step: BM=64, unrolled 3-stage pipeline, ldmatrix fragments =======
__global__ void __launch_bounds__(256) gate_step(int v)
{
    const int tid = threadIdx.x, warp = tid >> 5, lane = tid & 31;
    const int wm = warp & 1, wn = warp >> 1, g = lane >> 2, tg = lane & 3;
    const int bm = blockIdx.x * 64, bn = blockIdx.y * 64;
    const int cntv = g_cnt[v + 1];
    if (bm >= cntv) return;

    __shared__ __align__(16) __half As[3][64][24];
    __shared__ __align__(16) __half Bs[3][128][24];

    float acc[2][2][2][4];
#pragma unroll
    for (int gg = 0; gg < 2; ++gg)
#pragma unroll
        for (int mi = 0; mi < 2; ++mi)
#pragma unroll
            for (int ni = 0; ni < 2; ++ni)
#pragma unroll
                for (int q = 0; q < 4; ++q) acc[gg][mi][ni][q] = 0.f;

    {
        const uint32_t sA = (uint32_t)__cvta_generic_to_shared(&As[0][0][0]);
        const uint32_t sB = (uint32_t)__cvta_generic_to_shared(&Bs[0][0][0]);
        const int rowh = tid >> 1, half = tid & 1;
        const int gg0 = rowh >> 6, n0 = rowh & 63;
        const uint32_t lmoff = (uint32_t)((((lane >> 3) & 1) * 8 + (lane & 7)) * 48
                                          + (lane >> 4) * 16);
        const uint32_t aF = sA + lmoff + (uint32_t)(wm * 32) * 48;
        const uint32_t bF = sB + lmoff + (uint32_t)(wn * 16) * 48;
        const __half* pA = g_Hvh + (size_t)(bm + rowh) * KP + half * 8;
        const __half* pB = g_Wgm_h + (size_t)(gg0 * NPG + bn + n0) * KP + half * 8;

#pragma unroll
        for (int pre = 0; pre < 2; ++pre) {
            int k0 = pre * 16;
            if (tid < 128)
                cp16(sA + pre * 3072 + (uint32_t)(rowh * 48 + half * 16), pA + k0);
            cp16(sB + pre * 6144 + (uint32_t)(rowh * 48 + half * 16), pB + k0);
            CP_COMMIT;
        }
#pragma unroll
        for (int kt = 0; kt < NT; ++kt) {
            const int cur = kt % 3;
            if (kt == NT - 1) { CP_WAIT0; } else { CP_WAIT1; }
            __syncthreads();
            if (kt + 2 < NT) {
                const int nxt = (kt + 2) % 3;
                const int k0 = (kt + 2) * 16;
                if (tid < 128)
                    cp16(sA + nxt * 3072 + (uint32_t)(rowh * 48 + half * 16), pA + k0);
                cp16(sB + nxt * 6144 + (uint32_t)(rowh * 48 + half * 16), pB + k0);
                CP_COMMIT;
            }
            uint32_t a0[4], a1[4];
            ldsm4(a0, aF + cur * 3072);
            ldsm4(a1, aF + cur * 3072 + 768);
#pragma unroll
            for (int gg = 0; gg < 2; ++gg) {
                uint32_t b[4];
                ldsm4(b, bF + cur * 6144 + gg * 3072);
                MMA_F16(acc[gg][0][0], a0, b[0], b[2]);
                MMA_F16(acc[gg][0][1], a0, b[1], b[3]);
                MMA_F16(acc[gg][1][0], a1, b[0], b[2]);
                MMA_F16(acc[gg][1][1], a1, b[1], b[3]);
            }
        }
    }

    // ---- fused gate epilogue + Hin(v+1) ----
#pragma unroll
    for (int mi = 0; mi < 2; ++mi) {
#pragma unroll
        for (int rr = 0; rr < 2; ++rr) {
            int i = bm + wm * 32 + mi * 16 + g + rr * 8;
            int orig = g_perm[i];
            int pv = g_cid[orig * MAXN + v] % MAXPOS;
            unsigned mask = g_pmask[orig * MAXN + v + 1];
            int q0 = 2 * rr, q1 = 2 * rr + 1;
#pragma unroll
            for (int ni = 0; ni < 2; ++ni) {
                int j = bn + wn * 16 + ni * 8 + 2 * tg;
                if (j >= HS) continue;
                float2 gb = *(const float2*)(g_gateb + pv * KP + j);
                float2 mb = *(const float2*)(g_mapb + pv * KP + j);
                float gv0 = sigm(acc[0][mi][ni][q0] + gb.x) * (acc[1][mi][ni][q0] + mb.x);
                float gv1 = sigm(acc[0][mi][ni][q1] + gb.y) * (acc[1][mi][ni][q1] + mb.y);
                if (j + 1 >= HS) gv1 = 0.f;
                *(float2*)(g_gated + ((size_t)v * BSZ + i) * KP + j) = make_float2(gv0, gv1);
                float s0 = 0.f, s1 = 0.f;
                for (int u = 0; u < v; ++u)
                    if ((mask >> u) & 1u) {
                        float2 t = *(const float2*)(g_gated + ((size_t)u * BSZ + i) * KP + j);
                        s0 += t.x; s1 += t.y;
                    }
                if ((mask >> v) & 1u) { s0 += gv0; s1 += gv1; }
                *(float2*)(g_Hin + (size_t)i * KP + j) = make_float2(s0, s1);
                *(__half2*)&g_Hinh[(size_t)i * KP + j] = __floats2half2_rn(s0, s1);
            }
        }
    }
}

// ---------------- heads ----------------
__global__ void final_kernel(const float* __restrict__ Wmu, const float* __restrict__ bmu,
                             const float* __restrict__ Wlv, const float* __restrict__ blv,
                             float* __restrict__ out)
{
    __shared__ float sh[8][GS + 3];
    int b0 = blockIdx.x * 8;
    for (int idx = threadIdx.x; idx < 8 * HS; idx += blockDim.x) {
        int i = idx / HS, k = idx % HS;
        sh[i][k] = g_Hg[(size_t)(b0 + i) * HS + k];
    }
    for (int idx = threadIdx.x; idx < 8 * FEAT; idx += blockDim.x) {
        int i = idx / FEAT, f = idx % FEAT;
        sh[i][HS + f] = g_Hd[(b0 + i) * FEAT + f];
    }
    __syncthreads();
    int t = threadIdx.x;
    if (t < 2 * NZ) {
        int head = t / NZ;
        int o = t % NZ;
        const float* W = head ? Wlv : Wmu;
        float bias = head ? blv[o] : bmu[o];
        float acc[8];
#pragma unroll
        for (int i = 0; i < 8; ++i) acc[i] = 0.f;
        for (int k = 0; k < GS; ++k) {
            float wv = W[o * GS + k];
#pragma unroll
            for (int i = 0; i < 8; ++i) acc[i] += sh[i][k] * wv;
        }
#pragma unroll
        for (int i = 0; i < 8; ++i)
            out[(size_t)head * BSZ * NZ + (size_t)(b0 + i) * NZ + o] = acc[i] + bias;
    }
}

// ---------------- launch ----------------
extern "C" void kernel_launch(void* const* d_in, const int* in_sizes, int n_in,
                              void* d_out, int out_size)
{
    const int*   node_type = (const int*)  d_in[0];
    const int*   pos       = (const int*)  d_in[1];
    const int*   adj       = (const int*)  d_in[2];
    const int*   vcount    = (const int*)  d_in[3];
    const float* r         = (const float*)d_in[4];
    const float* c         = (const float*)d_in[5];
    const float* gm        = (const float*)d_in[6];
    const float* Wih       = (const float*)d_in[7];
    const float* Whh       = (const float*)d_in[8];
    const float* bih       = (const float*)d_in[9];
    const float* bhh       = (const float*)d_in[10];
    const float* Wg        = (const float*)d_in[11];
    const float* bg        = (const float*)d_in[12];
    const float* Wm        = (const float*)d_in[13];
    const float* W1        = (const float*)d_in[14];
    const float* b1        = (const float*)d_in[15];
    const float* W2        = (const float*)d_in[16];
    const float* b2        = (const float*)d_in[17];
    const float* Wmu       = (const float*)d_in[18];
    const float* bmu       = (const float*)d_in[19];
    const float* Wlv       = (const float*)d_in[20];
    const float* blv       = (const float*)d_in[21];
    float* out = (float*)d_out;

    const int tot_pack = (NG_GRU + NG_GATE) * KP + 2 * 9 * KP;
    const int pack_blocks = (tot_pack + 255) / 256;
    prep_kernel<<<16 + NCID + pack_blocks, 256>>>(
        vcount, node_type, pos, adj, r, c, gm, W1, b1, W2, b2,
        Wih, bih, bhh, Whh, Wg, bg, Wm);
    sort_kernel<<<1, 1024>>>();

    dim3 grid(64, 5);
    gru_step<<<grid, 256>>>(0, 0, bhh);
    for (int v = 0; v < 8; ++v) {
        gate_step<<<grid, 256>>>(v);
        gru_step<<<grid, 256>>>(v + 1, 1, bhh);
    }
    final_kernel<<<BSZ / 8, 128>>>(Wmu, bmu, Wlv, blv, out);
}